// round 1
// baseline (speedup 1.0000x reference)
#include <cuda_runtime.h>

// GraphConv (norm='both'): out = relu( D_in^-1/2 * A * (D_out^-1/2 h W) + b )
// N=100000 nodes, in_dim=256, out_dim=64, E=1.6M edges.
//
// Pipeline (5 kernels + 1 detect, all graph-capturable, no allocations):
//   k_detect : decide whether src/dst are int64 or int32 (jax x64 ambiguity)
//   k_zero   : zero d_out and degree arrays
//   k_degree : int histogram of src (out-deg) and dst (in-deg)
//   k_gemm   : x = (h * rsqrt(deg_out)) @ W   — fp32, f32x2 packed FMA, W in SMEM
//   k_scatter: d_out[dst] += x[src]           — float4 gather + 4 atomicAdd per thread
//   k_final  : d_out = relu(d_out * rsqrt(deg_in) + b)

#define NMAX 100000

__device__ float g_x[NMAX * 64];     // projected features, 25.6 MB (fits L2)
__device__ int   g_degout[NMAX];
__device__ int   g_degin[NMAX];
__device__ int   g_is64;

// ---------------------------------------------------------------------------
__global__ void k_detect(const int* __restrict__ src32) {
    if (blockIdx.x == 0 && threadIdx.x == 0) {
        // If data is int64 (values < 2^31), every high 32-bit word is 0.
        // If data is int32, odd positions are real node ids (all-zero prob ~0).
        int is64 = 1;
        #pragma unroll
        for (int i = 0; i < 32; i++)
            if (src32[2 * i + 1] != 0) is64 = 0;
        g_is64 = is64;
    }
}

__device__ __forceinline__ int load_idx(const void* p, int i, int is64) {
    if (is64) return (int)__ldg(((const long long*)p) + i);
    return __ldg(((const int*)p) + i);
}

// ---------------------------------------------------------------------------
__global__ void k_zero(float4* __restrict__ out4, int n4, int n_nodes) {
    int stride = gridDim.x * blockDim.x;
    int tid = blockIdx.x * blockDim.x + threadIdx.x;
    for (int j = tid; j < n4; j += stride)
        out4[j] = make_float4(0.f, 0.f, 0.f, 0.f);
    for (int j = tid; j < n_nodes; j += stride) {
        g_degout[j] = 0;
        g_degin[j]  = 0;
    }
}

// ---------------------------------------------------------------------------
__global__ void k_degree(const void* __restrict__ src, const void* __restrict__ dst, int E) {
    int is64 = g_is64;
    int stride = gridDim.x * blockDim.x;
    for (int e = blockIdx.x * blockDim.x + threadIdx.x; e < E; e += stride) {
        atomicAdd(&g_degout[load_idx(src, e, is64)], 1);
        atomicAdd(&g_degin[load_idx(dst, e, is64)], 1);
    }
}

// ---------------------------------------------------------------------------
// GEMM: x[n, 0:64] = (h[n, 0:256] * ns[n]) @ W[256, 64]
// Block: 256 threads, 32 nodes. thread -> (node = t>>3, colgroup = t&7 -> 8 cols)
// W fully staged in SMEM (64 KB), h rows staged scaled (32x260 padded).
// Inner loop: 1 LDS scalar (h) + 2 LDS.128 (W pairs) + 1 pack + 4 fma.rn.f32x2.
__global__ void __launch_bounds__(256, 2)
k_gemm(const float* __restrict__ h, const float* __restrict__ W, int n_nodes) {
    extern __shared__ float smem[];
    float* sW  = smem;                  // 256*64 floats, row k major, col contiguous
    float* sH  = smem + 256 * 64;       // 32 rows * 260 (pad) floats
    float* sNs = sH + 32 * 260;         // 32 floats

    int t = threadIdx.x;
    int base = blockIdx.x * 32;

    // stage W (4096 float4)
    const float4* W4 = (const float4*)W;
    float4* sW4 = (float4*)sW;
    for (int j = t; j < 4096; j += 256) sW4[j] = W4[j];

    if (t < 32) {
        int n = base + t;
        int dg = (n < n_nodes) ? g_degout[n] : 1;
        sNs[t] = rsqrtf((float)(dg > 1 ? dg : 1));
    }
    __syncthreads();

    // stage h rows, pre-scaled by norm_src (2048 float4)
    for (int j = t; j < 2048; j += 256) {
        int r  = j >> 6;
        int kc = (j & 63) << 2;
        int n  = base + r;
        float4 v = (n < n_nodes) ? __ldg((const float4*)(h + (size_t)n * 256 + kc))
                                 : make_float4(0.f, 0.f, 0.f, 0.f);
        float ns = sNs[r];
        float* dp = sH + r * 260 + kc;
        dp[0] = v.x * ns; dp[1] = v.y * ns; dp[2] = v.z * ns; dp[3] = v.w * ns;
    }
    __syncthreads();

    int node = t >> 3;     // 0..31
    int cg   = t & 7;      // cols cg*8 .. cg*8+7
    const float* hrow = sH + node * 260;

    unsigned long long a0 = 0ull, a1 = 0ull, a2 = 0ull, a3 = 0ull;  // {0.f,0.f}

    #pragma unroll 8
    for (int k = 0; k < 256; k++) {
        unsigned int hu = __float_as_uint(hrow[k]);
        unsigned long long h2;
        asm("mov.b64 %0, {%1, %1};" : "=l"(h2) : "r"(hu));
        const ulonglong2* wp = (const ulonglong2*)(sW + (k << 6) + (cg << 3));
        ulonglong2 wa = wp[0];   // cols +0,+1 | +2,+3
        ulonglong2 wb = wp[1];   // cols +4,+5 | +6,+7
        asm("fma.rn.f32x2 %0, %1, %2, %0;" : "+l"(a0) : "l"(h2), "l"(wa.x));
        asm("fma.rn.f32x2 %0, %1, %2, %0;" : "+l"(a1) : "l"(h2), "l"(wa.y));
        asm("fma.rn.f32x2 %0, %1, %2, %0;" : "+l"(a2) : "l"(h2), "l"(wb.x));
        asm("fma.rn.f32x2 %0, %1, %2, %0;" : "+l"(a3) : "l"(h2), "l"(wb.y));
    }

    int n = base + node;
    if (n < n_nodes) {
        ulonglong2* o = (ulonglong2*)(g_x + (size_t)n * 64 + (cg << 3));
        o[0] = make_ulonglong2(a0, a1);
        o[1] = make_ulonglong2(a2, a3);
    }
}

// ---------------------------------------------------------------------------
// 16 threads per edge, each thread: float4 gather from x[src], 4 atomicAdds to out[dst].
__global__ void k_scatter(const void* __restrict__ src, const void* __restrict__ dst,
                          float* __restrict__ out, int E) {
    int idx = blockIdx.x * blockDim.x + threadIdx.x;
    int e = idx >> 4;
    if (e >= E) return;
    int is64 = g_is64;
    int cg = idx & 15;
    int s = load_idx(src, e, is64);
    int d = load_idx(dst, e, is64);
    float4 v = *(const float4*)(g_x + (size_t)s * 64 + (cg << 2));
    float* o = out + (size_t)d * 64 + (cg << 2);
    atomicAdd(o + 0, v.x);
    atomicAdd(o + 1, v.y);
    atomicAdd(o + 2, v.z);
    atomicAdd(o + 3, v.w);
}

// ---------------------------------------------------------------------------
__global__ void k_final(float* __restrict__ out, const float* __restrict__ b, int n_nodes) {
    int idx = blockIdx.x * blockDim.x + threadIdx.x;
    int n = idx >> 4;
    if (n >= n_nodes) return;
    int cg = idx & 15;
    int dg = g_degin[n];
    float nd = rsqrtf((float)(dg > 1 ? dg : 1));
    float4 bb = __ldg((const float4*)(b + (cg << 2)));
    float4 v = *(float4*)(out + (size_t)n * 64 + (cg << 2));
    v.x = fmaxf(fmaf(v.x, nd, bb.x), 0.f);
    v.y = fmaxf(fmaf(v.y, nd, bb.y), 0.f);
    v.z = fmaxf(fmaf(v.z, nd, bb.z), 0.f);
    v.w = fmaxf(fmaf(v.w, nd, bb.w), 0.f);
    *(float4*)(out + (size_t)n * 64 + (cg << 2)) = v;
}

// ---------------------------------------------------------------------------
extern "C" void kernel_launch(void* const* d_in, const int* in_sizes, int n_in,
                              void* d_out, int out_size) {
    const float* h   = (const float*)d_in[0];
    const void*  src = d_in[1];
    const void*  dst = d_in[2];
    const float* W   = (const float*)d_in[3];
    const float* b   = (const float*)d_in[4];
    float* out = (float*)d_out;

    int n_nodes = in_sizes[0] / 256;
    int E = in_sizes[1];

    int smem_bytes = (256 * 64 + 32 * 260 + 32) * (int)sizeof(float);  // ~96.6 KB
    cudaFuncSetAttribute(k_gemm, cudaFuncAttributeMaxDynamicSharedMemorySize, smem_bytes);

    k_detect<<<1, 32>>>((const int*)src);
    k_zero<<<1024, 256>>>((float4*)out, n_nodes * 16, n_nodes);
    k_degree<<<2048, 256>>>(src, dst, E);
    k_gemm<<<(n_nodes + 31) / 32, 256, smem_bytes>>>(h, W, n_nodes);
    int tot = E * 16;
    k_scatter<<<(tot + 255) / 256, 256>>>(src, dst, out, E);
    k_final<<<(n_nodes * 16 + 255) / 256, 256>>>(out, b, n_nodes);
}

// round 2
// speedup vs baseline: 2.2933x; 2.2933x over previous
#include <cuda_runtime.h>

// GraphConv (norm='both'): out = relu( D_in^-1/2 * A * (h W) * D_out^-1/2-scaled + b )
// N=100000, in=256, out=64, E=1.6M.
//
// Pipeline: detect -> zero(degs) -> degree hist -> scan(3) -> csr fill ->
//           gemm (x = (h@W) * ns, register-blocked fp32 f32x2) ->
//           gather-reduce per dst node (fused *nd + b, relu)  [no float atomics]

#define NMAX 100000
#define EMAX 1600000

__device__ float g_x[NMAX * 64];       // projected features (25.6 MB, L2-resident)
__device__ int   g_degout[NMAX];
__device__ int   g_degin[NMAX];
__device__ int   g_ptr[NMAX + 1];      // CSR row pointers (by dst)
__device__ int   g_cursor[NMAX];
__device__ int   g_esrc[EMAX];         // CSR column indices (src per dst)
__device__ int   g_bsum[128];
__device__ int   g_boff[128];
__device__ int   g_is64;

// ---------------------------------------------------------------------------
__global__ void k_detect(const int* __restrict__ src32) {
    if (blockIdx.x == 0 && threadIdx.x == 0) {
        int is64 = 1;
        #pragma unroll
        for (int i = 0; i < 32; i++)
            if (src32[2 * i + 1] != 0) is64 = 0;
        g_is64 = is64;
    }
}

__device__ __forceinline__ int load_idx(const void* p, int i, int is64) {
    if (is64) return (int)__ldg(((const long long*)p) + i);
    return __ldg(((const int*)p) + i);
}

// ---------------------------------------------------------------------------
__global__ void k_zero(int n_nodes) {
    int stride = gridDim.x * blockDim.x;
    for (int j = blockIdx.x * blockDim.x + threadIdx.x; j < n_nodes; j += stride) {
        g_degout[j] = 0;
        g_degin[j]  = 0;
    }
}

// ---------------------------------------------------------------------------
__global__ void k_degree(const void* __restrict__ src, const void* __restrict__ dst, int E) {
    int is64 = g_is64;
    int stride = gridDim.x * blockDim.x;
    for (int e = blockIdx.x * blockDim.x + threadIdx.x; e < E; e += stride) {
        atomicAdd(&g_degout[load_idx(src, e, is64)], 1);
        atomicAdd(&g_degin[load_idx(dst, e, is64)], 1);
    }
}

// ---------------------------------------------------------------------------
// Exclusive scan of g_degin into g_ptr (3 kernels). NB <= 128 blocks of 1024.
__global__ void k_scan1(int n) {
    __shared__ int ws[32];
    int t = threadIdx.x;
    int i = blockIdx.x * 1024 + t;
    int v = (i < n) ? g_degin[i] : 0;
    int lane = t & 31, w = t >> 5;
    int x = v;
    #pragma unroll
    for (int o = 1; o < 32; o <<= 1) {
        int y = __shfl_up_sync(0xffffffffu, x, o);
        if (lane >= o) x += y;
    }
    if (lane == 31) ws[w] = x;
    __syncthreads();
    if (w == 0) {
        int s = ws[lane];
        #pragma unroll
        for (int o = 1; o < 32; o <<= 1) {
            int y = __shfl_up_sync(0xffffffffu, s, o);
            if (lane >= o) s += y;
        }
        ws[lane] = s;
    }
    __syncthreads();
    int off = (w > 0) ? ws[w - 1] : 0;
    int incl = x + off;
    if (i < n) g_ptr[i] = incl - v;
    if (t == 1023) g_bsum[blockIdx.x] = incl;
}

__global__ void k_scan2(int nb) {
    __shared__ int ws[4];
    int t = threadIdx.x;            // 128 threads
    int v = (t < nb) ? g_bsum[t] : 0;
    int lane = t & 31, w = t >> 5;
    int x = v;
    #pragma unroll
    for (int o = 1; o < 32; o <<= 1) {
        int y = __shfl_up_sync(0xffffffffu, x, o);
        if (lane >= o) x += y;
    }
    if (lane == 31) ws[w] = x;
    __syncthreads();
    if (w == 0 && lane < 4) {
        int s = ws[lane];
        #pragma unroll
        for (int o = 1; o < 4; o <<= 1) {
            int y = __shfl_up_sync(0xfu, s, o);
            if (lane >= o) s += y;
        }
        ws[lane] = s;
    }
    __syncthreads();
    int off = (w > 0) ? ws[w - 1] : 0;
    if (t < nb) g_boff[t] = (x + off) - v;
}

__global__ void k_scan3(int n, int E) {
    int i = blockIdx.x * blockDim.x + threadIdx.x;
    if (i < n) {
        int p = g_ptr[i] + g_boff[i >> 10];
        g_ptr[i] = p;
        g_cursor[i] = p;
    }
    if (i == 0) g_ptr[n] = E;
}

// ---------------------------------------------------------------------------
__global__ void k_fill(const void* __restrict__ src, const void* __restrict__ dst, int E) {
    int e = blockIdx.x * blockDim.x + threadIdx.x;
    if (e >= E) return;
    int is64 = g_is64;
    int d = load_idx(dst, e, is64);
    int s = load_idx(src, e, is64);
    int pos = atomicAdd(&g_cursor[d], 1);
    g_esrc[pos] = s;
}

// ---------------------------------------------------------------------------
// GEMM: x[n][0:64] = (h[n] @ W) * rsqrt(max(degout[n],1))
// Tile: 256 nodes x 64 cols, K chunked by 64. Thread: 8 nodes x 8 cols.
// f32x2 accumulators paired along columns (W pairs load directly as u64).
#define GCOLS 64
#define GKC   64
#define GKCP  68            // padded smem row stride for h
#define GNT   256

__global__ void __launch_bounds__(256)
k_gemm(const float* __restrict__ h, const float* __restrict__ W, int n_nodes) {
    extern __shared__ float smem[];
    float* sW  = smem;                   // GKC * GCOLS
    float* sH  = sW + GKC * GCOLS;       // GNT * GKCP
    float* sNs = sH + GNT * GKCP;        // GNT

    int t = threadIdx.x;
    int base = blockIdx.x * GNT;
    int cg8 = t & 7;                     // col group: cols cg8*8 .. +7
    int ln  = (t >> 3) * 8;              // first local node (8 nodes)

    {
        int n = base + t;
        int dg = (n < n_nodes) ? g_degout[n] : 1;
        sNs[t] = rsqrtf((float)(dg > 1 ? dg : 1));
    }

    unsigned long long acc[8][4];
    #pragma unroll
    for (int i = 0; i < 8; i++)
        #pragma unroll
        for (int j = 0; j < 4; j++) acc[i][j] = 0ull;

    for (int c = 0; c < 256 / GKC; c++) {
        int kc0 = c * GKC;
        __syncthreads();
        // stage W chunk: contiguous 16KB
        {
            const float4* Wg = (const float4*)(W + kc0 * GCOLS);
            float4* sW4 = (float4*)sW;
            #pragma unroll
            for (int i = 0; i < 4; i++) sW4[i * 256 + t] = Wg[i * 256 + t];
        }
        // stage h chunk: [node][k] padded rows (coalesced reads, conflict-free writes)
        #pragma unroll
        for (int i = 0; i < 16; i++) {
            int idx = i * 256 + t;
            int node = idx >> 4;
            int kq = idx & 15;
            int n = base + node;
            float4 v = (n < n_nodes)
                ? __ldg((const float4*)(h + (size_t)n * 256 + kc0 + kq * 4))
                : make_float4(0.f, 0.f, 0.f, 0.f);
            *(float4*)(sH + node * GKCP + kq * 4) = v;
        }
        __syncthreads();

        #pragma unroll
        for (int kk = 0; kk < GKC; kk += 4) {
            float4 hv[8];
            #pragma unroll
            for (int i = 0; i < 8; i++)
                hv[i] = *(const float4*)(sH + (ln + i) * GKCP + kk);
            #pragma unroll
            for (int d = 0; d < 4; d++) {
                const ulonglong2* wp = (const ulonglong2*)(sW + (kk + d) * GCOLS + cg8 * 8);
                ulonglong2 wa = wp[0];   // col pairs (0,1) (2,3)
                ulonglong2 wb = wp[1];   // col pairs (4,5) (6,7)
                #pragma unroll
                for (int i = 0; i < 8; i++) {
                    unsigned int hu = __float_as_uint(((const float*)&hv[i])[d]);
                    unsigned long long h2;
                    asm("mov.b64 %0, {%1, %1};" : "=l"(h2) : "r"(hu));
                    asm("fma.rn.f32x2 %0, %1, %2, %0;" : "+l"(acc[i][0]) : "l"(h2), "l"(wa.x));
                    asm("fma.rn.f32x2 %0, %1, %2, %0;" : "+l"(acc[i][1]) : "l"(h2), "l"(wa.y));
                    asm("fma.rn.f32x2 %0, %1, %2, %0;" : "+l"(acc[i][2]) : "l"(h2), "l"(wb.x));
                    asm("fma.rn.f32x2 %0, %1, %2, %0;" : "+l"(acc[i][3]) : "l"(h2), "l"(wb.y));
                }
            }
        }
    }

    // epilogue: scale by norm_src, store
    #pragma unroll
    for (int i = 0; i < 8; i++) {
        int n = base + ln + i;
        if (n < n_nodes) {
            unsigned int nsu = __float_as_uint(sNs[ln + i]);
            unsigned long long ns2;
            asm("mov.b64 %0, {%1, %1};" : "=l"(ns2) : "r"(nsu));
            unsigned long long r0, r1, r2, r3;
            asm("mul.rn.f32x2 %0, %1, %2;" : "=l"(r0) : "l"(acc[i][0]), "l"(ns2));
            asm("mul.rn.f32x2 %0, %1, %2;" : "=l"(r1) : "l"(acc[i][1]), "l"(ns2));
            asm("mul.rn.f32x2 %0, %1, %2;" : "=l"(r2) : "l"(acc[i][2]), "l"(ns2));
            asm("mul.rn.f32x2 %0, %1, %2;" : "=l"(r3) : "l"(acc[i][3]), "l"(ns2));
            ulonglong2* o = (ulonglong2*)(g_x + (size_t)n * 64 + cg8 * 8);
            o[0] = make_ulonglong2(r0, r1);
            o[1] = make_ulonglong2(r2, r3);
        }
    }
}

// ---------------------------------------------------------------------------
// One warp per dst node: acc = sum over in-edges of x[src], fused norm+bias+relu.
__global__ void k_gather(const float* __restrict__ b, float* __restrict__ out, int n_nodes) {
    int gw = (blockIdx.x * blockDim.x + threadIdx.x) >> 5;
    int l = threadIdx.x & 31;
    if (gw >= n_nodes) return;
    int p0 = g_ptr[gw], p1 = g_ptr[gw + 1];
    float ax = 0.f, ay = 0.f;
    int e = p0;
    for (; e + 1 < p1; e += 2) {
        int s0 = __ldg(&g_esrc[e]);
        int s1 = __ldg(&g_esrc[e + 1]);
        float2 v0 = ((const float2*)(g_x + (size_t)s0 * 64))[l];
        float2 v1 = ((const float2*)(g_x + (size_t)s1 * 64))[l];
        ax += v0.x + v1.x;
        ay += v0.y + v1.y;
    }
    if (e < p1) {
        int s = __ldg(&g_esrc[e]);
        float2 v = ((const float2*)(g_x + (size_t)s * 64))[l];
        ax += v.x;
        ay += v.y;
    }
    int deg = p1 - p0;
    float nd = rsqrtf((float)(deg > 1 ? deg : 1));
    float2 bb = __ldg((const float2*)b + l);
    float2 o;
    o.x = fmaxf(fmaf(ax, nd, bb.x), 0.f);
    o.y = fmaxf(fmaf(ay, nd, bb.y), 0.f);
    ((float2*)(out + (size_t)gw * 64))[l] = o;
}

// ---------------------------------------------------------------------------
extern "C" void kernel_launch(void* const* d_in, const int* in_sizes, int n_in,
                              void* d_out, int out_size) {
    const float* h   = (const float*)d_in[0];
    const void*  src = d_in[1];
    const void*  dst = d_in[2];
    const float* W   = (const float*)d_in[3];
    const float* b   = (const float*)d_in[4];
    float* out = (float*)d_out;

    int n_nodes = in_sizes[0] / 256;
    int E = in_sizes[1];
    int NB = (n_nodes + 1023) / 1024;

    int smem_bytes = (GKC * GCOLS + GNT * GKCP + GNT) * (int)sizeof(float);  // ~87 KB
    cudaFuncSetAttribute(k_gemm, cudaFuncAttributeMaxDynamicSharedMemorySize, smem_bytes);

    k_detect<<<1, 32>>>((const int*)src);
    k_zero<<<256, 256>>>(n_nodes);
    k_degree<<<2048, 256>>>(src, dst, E);
    k_scan1<<<NB, 1024>>>(n_nodes);
    k_scan2<<<1, 128>>>(NB);
    k_scan3<<<(n_nodes + 255) / 256, 256>>>(n_nodes, E);
    k_fill<<<(E + 255) / 256, 256>>>(src, dst, E);
    k_gemm<<<(n_nodes + GNT - 1) / GNT, 256, smem_bytes>>>(h, W, n_nodes);
    k_gather<<<(n_nodes * 32 + 255) / 256, 256>>>(b, out, n_nodes);
}

// round 3
// speedup vs baseline: 3.6852x; 1.6070x over previous
#include <cuda_runtime.h>

// GraphConv (norm='both'): out = relu( D_in^-1/2 * A * ((h W) * D_out^-1/2) + b )
// N=100000, in=256, out=64, E=1.6M.
//
// Pipeline: zero+detect -> degree hist -> scan(3) -> csr fill ->
//           gemm (fp32 f32x2, conflict-free smem) -> gather-reduce (fused epilogue)

#define NMAX 100000
#define EMAX 1600000

__device__ float g_x[NMAX * 64];       // projected features (25.6 MB, L2-resident)
__device__ int   g_degout[NMAX];
__device__ int   g_degin[NMAX];
__device__ int   g_ptr[NMAX + 1];      // CSR row pointers (by dst)
__device__ int   g_cursor[NMAX];
__device__ int   g_esrc[EMAX];         // CSR column indices (src per dst)
__device__ int   g_bsum[128];
__device__ int   g_boff[128];
__device__ int   g_is64;

__device__ __forceinline__ int load_idx(const void* p, int i, int is64) {
    if (is64) return (int)__ldg(((const long long*)p) + i);
    return __ldg(((const int*)p) + i);
}

// ---------------------------------------------------------------------------
__global__ void k_zero(const int* __restrict__ src32, int n_nodes) {
    if (blockIdx.x == 0 && threadIdx.x == 0) {
        int is64 = 1;
        #pragma unroll
        for (int i = 0; i < 32; i++)
            if (src32[2 * i + 1] != 0) is64 = 0;
        g_is64 = is64;
    }
    int stride = gridDim.x * blockDim.x;
    for (int j = blockIdx.x * blockDim.x + threadIdx.x; j < n_nodes; j += stride) {
        g_degout[j] = 0;
        g_degin[j]  = 0;
    }
}

// ---------------------------------------------------------------------------
__global__ void k_degree(const void* __restrict__ src, const void* __restrict__ dst, int E) {
    int is64 = g_is64;
    int stride = gridDim.x * blockDim.x;
    for (int e = blockIdx.x * blockDim.x + threadIdx.x; e < E; e += stride) {
        atomicAdd(&g_degout[load_idx(src, e, is64)], 1);
        atomicAdd(&g_degin[load_idx(dst, e, is64)], 1);
    }
}

// ---------------------------------------------------------------------------
// Exclusive scan of g_degin into g_ptr (3 kernels). NB <= 128 blocks of 1024.
__global__ void k_scan1(int n) {
    __shared__ int ws[32];
    int t = threadIdx.x;
    int i = blockIdx.x * 1024 + t;
    int v = (i < n) ? g_degin[i] : 0;
    int lane = t & 31, w = t >> 5;
    int x = v;
    #pragma unroll
    for (int o = 1; o < 32; o <<= 1) {
        int y = __shfl_up_sync(0xffffffffu, x, o);
        if (lane >= o) x += y;
    }
    if (lane == 31) ws[w] = x;
    __syncthreads();
    if (w == 0) {
        int s = ws[lane];
        #pragma unroll
        for (int o = 1; o < 32; o <<= 1) {
            int y = __shfl_up_sync(0xffffffffu, s, o);
            if (lane >= o) s += y;
        }
        ws[lane] = s;
    }
    __syncthreads();
    int off = (w > 0) ? ws[w - 1] : 0;
    int incl = x + off;
    if (i < n) g_ptr[i] = incl - v;
    if (t == 1023) g_bsum[blockIdx.x] = incl;
}

__global__ void k_scan2(int nb) {
    __shared__ int ws[4];
    int t = threadIdx.x;            // 128 threads
    int v = (t < nb) ? g_bsum[t] : 0;
    int lane = t & 31, w = t >> 5;
    int x = v;
    #pragma unroll
    for (int o = 1; o < 32; o <<= 1) {
        int y = __shfl_up_sync(0xffffffffu, x, o);
        if (lane >= o) x += y;
    }
    if (lane == 31) ws[w] = x;
    __syncthreads();
    if (w == 0 && lane < 4) {
        int s = ws[lane];
        #pragma unroll
        for (int o = 1; o < 4; o <<= 1) {
            int y = __shfl_up_sync(0xfu, s, o);
            if (lane >= o) s += y;
        }
        ws[lane] = s;
    }
    __syncthreads();
    int off = (w > 0) ? ws[w - 1] : 0;
    if (t < nb) g_boff[t] = (x + off) - v;
}

__global__ void k_scan3(int n, int E) {
    int i = blockIdx.x * blockDim.x + threadIdx.x;
    if (i < n) {
        int p = g_ptr[i] + g_boff[i >> 10];
        g_ptr[i] = p;
        g_cursor[i] = p;
    }
    if (i == 0) g_ptr[n] = E;
}

// ---------------------------------------------------------------------------
__global__ void k_fill(const void* __restrict__ src, const void* __restrict__ dst, int E) {
    int e = blockIdx.x * blockDim.x + threadIdx.x;
    if (e >= E) return;
    int is64 = g_is64;
    int d = load_idx(dst, e, is64);
    int s = load_idx(src, e, is64);
    int pos = atomicAdd(&g_cursor[d], 1);
    g_esrc[pos] = s;
}

// ---------------------------------------------------------------------------
// GEMM: x[n][0:64] = (h[n] @ W) * rsqrt(max(degout[n],1))
// Tile: 256 nodes x 64 cols, K chunked by 64. Thread: 8 nodes (strided 32) x 8 cols.
// Conflict-free smem:
//   sH: [node][68]  -> warp's 4 distinct rows differ by 68 ≡ 4 (mod 32 banks)
//   sW: two planes [p][k][cg]*16B -> warp reads 128B contiguous per (k, plane)
#define GCOLS 64
#define GKC   64
#define GKCP  68
#define GNT   256

__global__ void __launch_bounds__(256, 2)
k_gemm(const float* __restrict__ h, const float* __restrict__ W, int n_nodes) {
    extern __shared__ float smem[];
    float* sW  = smem;                   // 2 * GKC * 32 floats = 16 KB
    float* sH  = sW + 2 * GKC * 32;      // GNT * GKCP floats  = 69.6 KB
    float* sNs = sH + GNT * GKCP;        // GNT floats

    int t = threadIdx.x;
    int base = blockIdx.x * GNT;
    int cg8 = t & 7;                     // col group: cols cg8*8 .. +7
    int lt  = t >> 3;                    // 0..31; nodes lt, lt+32, ..., lt+224

    {
        int n = base + t;
        int dg = (n < n_nodes) ? g_degout[n] : 1;
        sNs[t] = rsqrtf((float)(dg > 1 ? dg : 1));
    }

    unsigned long long acc[8][4];
    #pragma unroll
    for (int i = 0; i < 8; i++)
        #pragma unroll
        for (int j = 0; j < 4; j++) acc[i][j] = 0ull;

    for (int c = 0; c < 256 / GKC; c++) {
        int kc0 = c * GKC;
        __syncthreads();
        // stage W chunk into two 16B planes: plane p holds cols 8cg+4p .. 8cg+4p+3
        {
            const float4* Wg = (const float4*)(W + kc0 * GCOLS);
            float4* sW4 = (float4*)sW;
            #pragma unroll
            for (int i = 0; i < 4; i++) {
                int j = i * 256 + t;          // 0..1023
                int k  = j >> 4;
                int c4 = j & 15;
                int p  = c4 & 1;
                int cg = c4 >> 1;
                sW4[p * GKC * 8 + k * 8 + cg] = Wg[j];
            }
        }
        // stage h chunk: [node][k] padded rows
        #pragma unroll
        for (int i = 0; i < 16; i++) {
            int idx = i * 256 + t;
            int node = idx >> 4;
            int kq = idx & 15;
            int n = base + node;
            float4 v = (n < n_nodes)
                ? __ldg((const float4*)(h + (size_t)n * 256 + kc0 + kq * 4))
                : make_float4(0.f, 0.f, 0.f, 0.f);
            *(float4*)(sH + node * GKCP + kq * 4) = v;
        }
        __syncthreads();

        #pragma unroll 4
        for (int kk = 0; kk < GKC; kk += 4) {
            float4 hv[8];
            #pragma unroll
            for (int i = 0; i < 8; i++)
                hv[i] = *(const float4*)(sH + (lt + 32 * i) * GKCP + kk);
            #pragma unroll
            for (int d = 0; d < 4; d++) {
                ulonglong2 wa = *(const ulonglong2*)(sW + (kk + d) * 32 + cg8 * 4);
                ulonglong2 wb = *(const ulonglong2*)(sW + GKC * 32 + (kk + d) * 32 + cg8 * 4);
                #pragma unroll
                for (int i = 0; i < 8; i++) {
                    unsigned int hu = __float_as_uint(((const float*)&hv[i])[d]);
                    unsigned long long h2;
                    asm("mov.b64 %0, {%1, %1};" : "=l"(h2) : "r"(hu));
                    asm("fma.rn.f32x2 %0, %1, %2, %0;" : "+l"(acc[i][0]) : "l"(h2), "l"(wa.x));
                    asm("fma.rn.f32x2 %0, %1, %2, %0;" : "+l"(acc[i][1]) : "l"(h2), "l"(wa.y));
                    asm("fma.rn.f32x2 %0, %1, %2, %0;" : "+l"(acc[i][2]) : "l"(h2), "l"(wb.x));
                    asm("fma.rn.f32x2 %0, %1, %2, %0;" : "+l"(acc[i][3]) : "l"(h2), "l"(wb.y));
                }
            }
        }
    }

    // epilogue: scale by norm_src, store
    #pragma unroll
    for (int i = 0; i < 8; i++) {
        int n = base + lt + 32 * i;
        if (n < n_nodes) {
            unsigned int nsu = __float_as_uint(sNs[lt + 32 * i]);
            unsigned long long ns2;
            asm("mov.b64 %0, {%1, %1};" : "=l"(ns2) : "r"(nsu));
            unsigned long long r0, r1, r2, r3;
            asm("mul.rn.f32x2 %0, %1, %2;" : "=l"(r0) : "l"(acc[i][0]), "l"(ns2));
            asm("mul.rn.f32x2 %0, %1, %2;" : "=l"(r1) : "l"(acc[i][1]), "l"(ns2));
            asm("mul.rn.f32x2 %0, %1, %2;" : "=l"(r2) : "l"(acc[i][2]), "l"(ns2));
            asm("mul.rn.f32x2 %0, %1, %2;" : "=l"(r3) : "l"(acc[i][3]), "l"(ns2));
            ulonglong2* o = (ulonglong2*)(g_x + (size_t)n * 64 + cg8 * 8);
            o[0] = make_ulonglong2(r0, r1);
            o[1] = make_ulonglong2(r2, r3);
        }
    }
}

// ---------------------------------------------------------------------------
// One warp per dst node. Unroll-4 for MLP against L2 latency.
__global__ void k_gather(const float* __restrict__ b, float* __restrict__ out, int n_nodes) {
    int gw = (blockIdx.x * blockDim.x + threadIdx.x) >> 5;
    int l = threadIdx.x & 31;
    if (gw >= n_nodes) return;
    int p0 = g_ptr[gw], p1 = g_ptr[gw + 1];
    float ax = 0.f, ay = 0.f;
    int e = p0;
    for (; e + 3 < p1; e += 4) {
        int s0 = __ldg(&g_esrc[e]);
        int s1 = __ldg(&g_esrc[e + 1]);
        int s2 = __ldg(&g_esrc[e + 2]);
        int s3 = __ldg(&g_esrc[e + 3]);
        float2 v0 = ((const float2*)(g_x + (size_t)s0 * 64))[l];
        float2 v1 = ((const float2*)(g_x + (size_t)s1 * 64))[l];
        float2 v2 = ((const float2*)(g_x + (size_t)s2 * 64))[l];
        float2 v3 = ((const float2*)(g_x + (size_t)s3 * 64))[l];
        ax += (v0.x + v1.x) + (v2.x + v3.x);
        ay += (v0.y + v1.y) + (v2.y + v3.y);
    }
    for (; e < p1; e++) {
        int s = __ldg(&g_esrc[e]);
        float2 v = ((const float2*)(g_x + (size_t)s * 64))[l];
        ax += v.x;
        ay += v.y;
    }
    int deg = p1 - p0;
    float nd = rsqrtf((float)(deg > 1 ? deg : 1));
    float2 bb = __ldg((const float2*)b + l);
    float2 o;
    o.x = fmaxf(fmaf(ax, nd, bb.x), 0.f);
    o.y = fmaxf(fmaf(ay, nd, bb.y), 0.f);
    ((float2*)(out + (size_t)gw * 64))[l] = o;
}

// ---------------------------------------------------------------------------
extern "C" void kernel_launch(void* const* d_in, const int* in_sizes, int n_in,
                              void* d_out, int out_size) {
    const float* h   = (const float*)d_in[0];
    const void*  src = d_in[1];
    const void*  dst = d_in[2];
    const float* W   = (const float*)d_in[3];
    const float* b   = (const float*)d_in[4];
    float* out = (float*)d_out;

    int n_nodes = in_sizes[0] / 256;
    int E = in_sizes[1];
    int NB = (n_nodes + 1023) / 1024;

    int smem_bytes = (2 * GKC * 32 + GNT * GKCP + GNT) * (int)sizeof(float);  // ~86 KB
    cudaFuncSetAttribute(k_gemm, cudaFuncAttributeMaxDynamicSharedMemorySize, smem_bytes);

    k_zero<<<256, 256>>>((const int*)src, n_nodes);
    k_degree<<<2048, 256>>>(src, dst, E);
    k_scan1<<<NB, 1024>>>(n_nodes);
    k_scan2<<<1, 128>>>(NB);
    k_scan3<<<(n_nodes + 255) / 256, 256>>>(n_nodes, E);
    k_fill<<<(E + 255) / 256, 256>>>(src, dst, E);
    k_gemm<<<(n_nodes + GNT - 1) / GNT, 256, smem_bytes>>>(h, W, n_nodes);
    k_gather<<<(n_nodes * 32 + 255) / 256, 256>>>(b, out, n_nodes);
}

// round 4
// speedup vs baseline: 4.3766x; 1.1876x over previous
#include <cuda_runtime.h>
#include <cuda_fp16.h>

// GraphConv (norm='both'): out = relu( D_in^-1/2 * A * ((h W) * D_out^-1/2) + b )
// N=100000, in=256, out=64, E=1.6M.
//
// Pipeline (graph with fork):
//   stream0: zero+detect -> degree -> [e1] -> gemm ----------------\
//   s2:                         [e1] -> scan(lookback) -> fill -> [e2]
//   stream0: (wait e2) -> gather
// x stored fp16 (halves gather L2 traffic); all accumulation fp32.

#define NMAX 100000
#define EMAX 1600000

__device__ __half g_x[NMAX * 64];      // projected features, fp16 (12.8 MB, L2-resident)
__device__ int    g_degout[NMAX];
__device__ int    g_degin[NMAX];
__device__ int    g_ptr[NMAX + 1];     // CSR row pointers (by dst)
__device__ int    g_cursor[NMAX];
__device__ int    g_esrc[EMAX];        // CSR column indices (src per dst)
__device__ int    g_state[128];        // decoupled-lookback states
__device__ int    g_is64;

__device__ __forceinline__ int load_idx(const void* p, int i, int is64) {
    if (is64) return (int)__ldg(((const long long*)p) + i);
    return __ldg(((const int*)p) + i);
}

// ---------------------------------------------------------------------------
__global__ void k_zero(const int* __restrict__ src32, int n_nodes) {
    int tid = blockIdx.x * blockDim.x + threadIdx.x;
    if (tid == 0) {
        int is64 = 1;
        #pragma unroll
        for (int i = 0; i < 32; i++)
            if (src32[2 * i + 1] != 0) is64 = 0;
        g_is64 = is64;
    }
    if (tid < 128) g_state[tid] = 0;
    int stride = gridDim.x * blockDim.x;
    for (int j = tid; j < n_nodes; j += stride) {
        g_degout[j] = 0;
        g_degin[j]  = 0;
    }
}

// ---------------------------------------------------------------------------
__global__ void k_degree(const void* __restrict__ src, const void* __restrict__ dst, int E) {
    int is64 = g_is64;
    int stride = gridDim.x * blockDim.x;
    for (int e = blockIdx.x * blockDim.x + threadIdx.x; e < E; e += stride) {
        atomicAdd(&g_degout[load_idx(src, e, is64)], 1);
        atomicAdd(&g_degin[load_idx(dst, e, is64)], 1);
    }
}

// ---------------------------------------------------------------------------
// Single-pass exclusive scan of g_degin -> g_ptr/g_cursor (decoupled lookback).
// <=128 blocks, all resident (148 SMs) -> spin is safe. Value fits 21 bits.
#define FLAG_A (1 << 30)
#define FLAG_P (2 << 30)
__global__ void k_scan(int n, int E) {
    __shared__ int ws[32];
    __shared__ int s_prefix;
    int t = threadIdx.x, blk = blockIdx.x;
    int i = blk * 1024 + t;
    int v = (i < n) ? g_degin[i] : 0;
    int lane = t & 31, w = t >> 5;
    int x = v;
    #pragma unroll
    for (int o = 1; o < 32; o <<= 1) {
        int y = __shfl_up_sync(0xffffffffu, x, o);
        if (lane >= o) x += y;
    }
    if (lane == 31) ws[w] = x;
    __syncthreads();
    if (w == 0) {
        int s = ws[lane];
        #pragma unroll
        for (int o = 1; o < 32; o <<= 1) {
            int y = __shfl_up_sync(0xffffffffu, s, o);
            if (lane >= o) s += y;
        }
        ws[lane] = s;
    }
    __syncthreads();
    int off = (w > 0) ? ws[w - 1] : 0;
    int incl = x + off;                 // inclusive within block

    if (t == 1023) {
        int agg = incl;
        if (blk == 0) {
            atomicExch(&g_state[0], FLAG_P | agg);
            s_prefix = 0;
        } else {
            atomicExch(&g_state[blk], FLAG_A | agg);
            int ex = 0;
            int p = blk - 1;
            while (true) {
                int st;
                do { st = atomicAdd(&g_state[p], 0); } while ((st >> 30) == 0);
                ex += st & 0x3FFFFFFF;
                if (st & FLAG_P) break;
                p--;
            }
            atomicExch(&g_state[blk], FLAG_P | (ex + agg));
            s_prefix = ex;
        }
    }
    __syncthreads();
    int pfx = s_prefix;
    int pv = incl - v + pfx;
    if (i < n) {
        g_ptr[i] = pv;
        g_cursor[i] = pv;
    }
    if (i == 0) g_ptr[n] = E;
}

// ---------------------------------------------------------------------------
__global__ void k_fill(const void* __restrict__ src, const void* __restrict__ dst, int E) {
    int e = blockIdx.x * blockDim.x + threadIdx.x;
    if (e >= E) return;
    int is64 = g_is64;
    int d = load_idx(dst, e, is64);
    int s = load_idx(src, e, is64);
    int pos = atomicAdd(&g_cursor[d], 1);
    g_esrc[pos] = s;
}

// ---------------------------------------------------------------------------
// GEMM: x[n][0:64] = fp16( (h[n] @ W) * rsqrt(max(degout[n],1)) )
// Tile: 256 nodes x 64 cols, K chunked by 64. Thread: 8 nodes (strided 32) x 8 cols.
// Conflict-free smem (sH rows stride 68 == 4 mod 32; sW two 16B planes).
#define GCOLS 64
#define GKC   64
#define GKCP  68
#define GNT   256

__global__ void __launch_bounds__(256, 2)
k_gemm(const float* __restrict__ h, const float* __restrict__ W, int n_nodes) {
    extern __shared__ float smem[];
    float* sW  = smem;                   // 2 * GKC * 32 floats = 16 KB
    float* sH  = sW + 2 * GKC * 32;      // GNT * GKCP floats  = 69.6 KB
    float* sNs = sH + GNT * GKCP;        // GNT floats

    int t = threadIdx.x;
    int base = blockIdx.x * GNT;
    int cg8 = t & 7;
    int lt  = t >> 3;

    {
        int n = base + t;
        int dg = (n < n_nodes) ? g_degout[n] : 1;
        sNs[t] = rsqrtf((float)(dg > 1 ? dg : 1));
    }

    unsigned long long acc[8][4];
    #pragma unroll
    for (int i = 0; i < 8; i++)
        #pragma unroll
        for (int j = 0; j < 4; j++) acc[i][j] = 0ull;

    for (int c = 0; c < 256 / GKC; c++) {
        int kc0 = c * GKC;
        __syncthreads();
        {
            const float4* Wg = (const float4*)(W + kc0 * GCOLS);
            float4* sW4 = (float4*)sW;
            #pragma unroll
            for (int i = 0; i < 4; i++) {
                int j = i * 256 + t;
                int k  = j >> 4;
                int c4 = j & 15;
                int p  = c4 & 1;
                int cg = c4 >> 1;
                sW4[p * GKC * 8 + k * 8 + cg] = Wg[j];
            }
        }
        #pragma unroll
        for (int i = 0; i < 16; i++) {
            int idx = i * 256 + t;
            int node = idx >> 4;
            int kq = idx & 15;
            int n = base + node;
            float4 v = (n < n_nodes)
                ? __ldg((const float4*)(h + (size_t)n * 256 + kc0 + kq * 4))
                : make_float4(0.f, 0.f, 0.f, 0.f);
            *(float4*)(sH + node * GKCP + kq * 4) = v;
        }
        __syncthreads();

        #pragma unroll 4
        for (int kk = 0; kk < GKC; kk += 4) {
            float4 hv[8];
            #pragma unroll
            for (int i = 0; i < 8; i++)
                hv[i] = *(const float4*)(sH + (lt + 32 * i) * GKCP + kk);
            #pragma unroll
            for (int d = 0; d < 4; d++) {
                ulonglong2 wa = *(const ulonglong2*)(sW + (kk + d) * 32 + cg8 * 4);
                ulonglong2 wb = *(const ulonglong2*)(sW + GKC * 32 + (kk + d) * 32 + cg8 * 4);
                #pragma unroll
                for (int i = 0; i < 8; i++) {
                    unsigned int hu = __float_as_uint(((const float*)&hv[i])[d]);
                    unsigned long long h2;
                    asm("mov.b64 %0, {%1, %1};" : "=l"(h2) : "r"(hu));
                    asm("fma.rn.f32x2 %0, %1, %2, %0;" : "+l"(acc[i][0]) : "l"(h2), "l"(wa.x));
                    asm("fma.rn.f32x2 %0, %1, %2, %0;" : "+l"(acc[i][1]) : "l"(h2), "l"(wa.y));
                    asm("fma.rn.f32x2 %0, %1, %2, %0;" : "+l"(acc[i][2]) : "l"(h2), "l"(wb.x));
                    asm("fma.rn.f32x2 %0, %1, %2, %0;" : "+l"(acc[i][3]) : "l"(h2), "l"(wb.y));
                }
            }
        }
    }

    #pragma unroll
    for (int i = 0; i < 8; i++) {
        int n = base + lt + 32 * i;
        if (n < n_nodes) {
            unsigned int nsu = __float_as_uint(sNs[lt + 32 * i]);
            unsigned long long ns2;
            asm("mov.b64 %0, {%1, %1};" : "=l"(ns2) : "r"(nsu));
            unsigned long long r0, r1, r2, r3;
            asm("mul.rn.f32x2 %0, %1, %2;" : "=l"(r0) : "l"(acc[i][0]), "l"(ns2));
            asm("mul.rn.f32x2 %0, %1, %2;" : "=l"(r1) : "l"(acc[i][1]), "l"(ns2));
            asm("mul.rn.f32x2 %0, %1, %2;" : "=l"(r2) : "l"(acc[i][2]), "l"(ns2));
            asm("mul.rn.f32x2 %0, %1, %2;" : "=l"(r3) : "l"(acc[i][3]), "l"(ns2));
            __half2 q0 = __float22half2_rn(*(float2*)&r0);
            __half2 q1 = __float22half2_rn(*(float2*)&r1);
            __half2 q2 = __float22half2_rn(*(float2*)&r2);
            __half2 q3 = __float22half2_rn(*(float2*)&r3);
            uint4 pk;
            pk.x = *(unsigned int*)&q0;
            pk.y = *(unsigned int*)&q1;
            pk.z = *(unsigned int*)&q2;
            pk.w = *(unsigned int*)&q3;
            *(uint4*)(g_x + (size_t)n * 64 + cg8 * 8) = pk;
        }
    }
}

// ---------------------------------------------------------------------------
// One warp per dst node; fp16 rows (128B/edge), fp32 accumulate, fused epilogue.
__global__ void k_gather(const float* __restrict__ b, float* __restrict__ out, int n_nodes) {
    int gw = (blockIdx.x * blockDim.x + threadIdx.x) >> 5;
    int l = threadIdx.x & 31;
    if (gw >= n_nodes) return;
    int p0 = g_ptr[gw], p1 = g_ptr[gw + 1];
    float ax = 0.f, ay = 0.f;
    int e = p0;
    for (; e + 3 < p1; e += 4) {
        int s0 = __ldg(&g_esrc[e]);
        int s1 = __ldg(&g_esrc[e + 1]);
        int s2 = __ldg(&g_esrc[e + 2]);
        int s3 = __ldg(&g_esrc[e + 3]);
        __half2 v0 = ((const __half2*)(g_x + (size_t)s0 * 64))[l];
        __half2 v1 = ((const __half2*)(g_x + (size_t)s1 * 64))[l];
        __half2 v2 = ((const __half2*)(g_x + (size_t)s2 * 64))[l];
        __half2 v3 = ((const __half2*)(g_x + (size_t)s3 * 64))[l];
        float2 f0 = __half22float2(v0);
        float2 f1 = __half22float2(v1);
        float2 f2 = __half22float2(v2);
        float2 f3 = __half22float2(v3);
        ax += (f0.x + f1.x) + (f2.x + f3.x);
        ay += (f0.y + f1.y) + (f2.y + f3.y);
    }
    for (; e < p1; e++) {
        int s = __ldg(&g_esrc[e]);
        float2 f = __half22float2(((const __half2*)(g_x + (size_t)s * 64))[l]);
        ax += f.x;
        ay += f.y;
    }
    int deg = p1 - p0;
    float nd = rsqrtf((float)(deg > 1 ? deg : 1));
    float2 bb = __ldg((const float2*)b + l);
    float2 o;
    o.x = fmaxf(fmaf(ax, nd, bb.x), 0.f);
    o.y = fmaxf(fmaf(ay, nd, bb.y), 0.f);
    ((float2*)(out + (size_t)gw * 64))[l] = o;
}

// ---------------------------------------------------------------------------
extern "C" void kernel_launch(void* const* d_in, const int* in_sizes, int n_in,
                              void* d_out, int out_size) {
    const float* h   = (const float*)d_in[0];
    const void*  src = d_in[1];
    const void*  dst = d_in[2];
    const float* W   = (const float*)d_in[3];
    const float* b   = (const float*)d_in[4];
    float* out = (float*)d_out;

    int n_nodes = in_sizes[0] / 256;
    int E = in_sizes[1];
    int NB = (n_nodes + 1023) / 1024;

    static cudaStream_t s2 = nullptr;
    static cudaEvent_t e1 = nullptr, e2 = nullptr;
    if (!s2) {
        cudaStreamCreateWithFlags(&s2, cudaStreamNonBlocking);
        cudaEventCreateWithFlags(&e1, cudaEventDisableTiming);
        cudaEventCreateWithFlags(&e2, cudaEventDisableTiming);
    }

    int smem_bytes = (2 * GKC * 32 + GNT * GKCP + GNT) * (int)sizeof(float);  // ~86 KB
    cudaFuncSetAttribute(k_gemm, cudaFuncAttributeMaxDynamicSharedMemorySize, smem_bytes);

    // main (capture) stream
    k_zero<<<256, 256>>>((const int*)src, n_nodes);
    k_degree<<<2048, 256>>>(src, dst, E);
    cudaEventRecord(e1, 0);

    // forked branch: CSR build runs concurrently with GEMM
    cudaStreamWaitEvent(s2, e1, 0);
    k_scan<<<NB, 1024, 0, s2>>>(n_nodes, E);
    k_fill<<<(E + 255) / 256, 256, 0, s2>>>(src, dst, E);
    cudaEventRecord(e2, s2);

    // main stream: GEMM overlaps the branch, then join and gather
    k_gemm<<<(n_nodes + GNT - 1) / GNT, 256, smem_bytes>>>(h, W, n_nodes);
    cudaStreamWaitEvent(0, e2, 0);
    k_gather<<<(n_nodes * 32 + 255) / 256, 256>>>(b, out, n_nodes);
}